// round 8
// baseline (speedup 1.0000x reference)
#include <cuda_runtime.h>
#include <math.h>

// ---------------------------------------------------------------------------
// DRMM matching score, GB300 (sm_103a) — round 8: lean scalar FFMA
//   Facts established: tcgen05 uncompilable (compute_103 target); legacy HMMA
//   ~1/16 rate on this die; fma.rn.f32x2 gives no FLOP gain; R6 LDS pattern
//   had 4-way conflicts. -> close the gap to the 67us scalar FFMA floor.
//   * float4 broadcast q loads (rows padded to 52 floats, 16B aligned)
//   * 8 independent FFMA chains per q (2 d-rows x 4 chains)
//   * match_any-aggregated smem histogram (R1-proven), per-tile slices
//   * gating branch dropped: softmax over batch sums to exactly 1
//   * 5 launches/call so ncu -s 5 -c 1 profiles simhist (idx5 = call2 pos0)
// ---------------------------------------------------------------------------

#define BB   256
#define QQ   50
#define EE   50
#define DD   2000
#define NB   11
#define QB   (QQ * NB)        // 550
#define NTHREADS 128
#define TROWS 256             // d-rows per CTA (2 per thread)
#define NTILE 8               // 8*256 = 2048 >= 2000
#define QROW 52               // padded floats per q row (13 float4, 208B rows)

__device__ int g_part[NTILE * BB * QB];   // per-(tile,batch) histogram slices

__global__ void nop_kernel() {}

// ---------------------------------------------------------------------------
// Main kernel: grid (NTILE, BB), 128 threads. Thread owns d-rows (t, t+128).
// ---------------------------------------------------------------------------
__global__ void __launch_bounds__(NTHREADS, 3)
simhist_kernel(const float* __restrict__ qemb,
               const float* __restrict__ demb,
               const int*   __restrict__ qids,
               const int*   __restrict__ dids)
{
    __shared__ __align__(16) float qs[QQ * QROW];   // normalized q rows
    __shared__ int hist_s[QB];
    __shared__ unsigned char qv_s[QQ];

    const int b    = blockIdx.y;
    const int tile = blockIdx.x;
    const int t    = threadIdx.x;
    const int lane = t & 31;

    // ---- stage raw q tile (float2 rows into 52-float rows) ----
    {
        const float2* qsrc = (const float2*)(qemb + (size_t)b * QQ * EE);
        for (int i = t; i < QQ * 25; i += NTHREADS)
            ((float2*)qs)[(i / 25) * 26 + (i % 25)] = qsrc[i];
        for (int i = t; i < QB; i += NTHREADS) hist_s[i] = 0;
    }

    // ---- load this thread's 2 d-rows, normalize into registers ----
    const int dA = tile * TROWS + t;
    const int dB = dA + NTHREADS;
    const bool okA = (dA < DD);
    const bool okB = (dB < DD);
    float a0[52], a1[52];
    {
        const float2* pA = (const float2*)(demb + ((size_t)b * DD + (okA ? dA : 0)) * EE);
        const float2* pB = (const float2*)(demb + ((size_t)b * DD + (okB ? dB : 0)) * EE);
        float ssA = 0.f, ssB = 0.f;
#pragma unroll
        for (int c = 0; c < 25; c++) {
            float2 v = okA ? pA[c] : make_float2(0.f, 0.f);
            a0[2 * c] = v.x; a0[2 * c + 1] = v.y;
            ssA += v.x * v.x + v.y * v.y;
            float2 w = okB ? pB[c] : make_float2(0.f, 0.f);
            a1[2 * c] = w.x; a1[2 * c + 1] = w.y;
            ssB += w.x * w.x + w.y * w.y;
        }
        a0[50] = a0[51] = 0.f; a1[50] = a1[51] = 0.f;
        const float rA = 1.0f / (sqrtf(ssA) + 1e-8f);
        const float rB = 1.0f / (sqrtf(ssB) + 1e-8f);
#pragma unroll
        for (int e = 0; e < 50; e++) { a0[e] *= rA; a1[e] *= rB; }
    }
    const bool addA = okA && (dids[b * DD + (okA ? dA : 0)] > 0);
    const bool addB = okB && (dids[b * DD + (okB ? dB : 0)] > 0);
    const unsigned vbA = __ballot_sync(0xffffffffu, addA);
    const unsigned vbB = __ballot_sync(0xffffffffu, addB);

    __syncthreads();

    // ---- normalize q rows in place (threads 0..49), pad, validity ----
    if (t < QQ) {
        float* r = &qs[t * QROW];
        float ss = 0.f;
#pragma unroll
        for (int e = 0; e < EE; e++) ss += r[e] * r[e];
        const float rq = 1.0f / (sqrtf(ss) + 1e-8f);
#pragma unroll
        for (int e = 0; e < EE; e++) r[e] *= rq;
        r[50] = 0.f; r[51] = 0.f;
        qv_s[t] = (qids[b * QQ + t] > 0) ? 1 : 0;
    }
    __syncthreads();

    // ---- mainloop: per q, 13 LDS.128 + 100 FFMA in 8 chains ----
    for (int q = 0; q < QQ; q++) {
        if (!qv_s[q]) continue;                     // uniform branch
        const float4* w = (const float4*)&qs[q * QROW];
        float s0 = 0.f, s1 = 0.f, s2 = 0.f, s3 = 0.f;
        float u0 = 0.f, u1 = 0.f, u2 = 0.f, u3 = 0.f;
#pragma unroll
        for (int c = 0; c < 13; c++) {
            float4 wv = w[c];                       // broadcast LDS.128
            s0 = fmaf(a0[4 * c],     wv.x, s0);
            s1 = fmaf(a0[4 * c + 1], wv.y, s1);
            s2 = fmaf(a0[4 * c + 2], wv.z, s2);
            s3 = fmaf(a0[4 * c + 3], wv.w, s3);
            u0 = fmaf(a1[4 * c],     wv.x, u0);
            u1 = fmaf(a1[4 * c + 1], wv.y, u1);
            u2 = fmaf(a1[4 * c + 2], wv.z, u2);
            u3 = fmaf(a1[4 * c + 3], wv.w, u3);
        }
        const int base = q * NB;

        float simA = (s0 + s1) + (s2 + s3);
        int binA = (int)fmaf(simA, 5.0f, 5.000005f);
        binA = min(max(binA, 0), NB - 1);
        unsigned mA = __match_any_sync(0xffffffffu, binA) & vbA;
        if (addA && lane == (int)(__ffs(mA) - 1))
            atomicAdd(&hist_s[base + binA], (int)__popc(mA));

        float simB = (u0 + u1) + (u2 + u3);
        int binB = (int)fmaf(simB, 5.0f, 5.000005f);
        binB = min(max(binB, 0), NB - 1);
        unsigned mB = __match_any_sync(0xffffffffu, binB) & vbB;
        if (addB && lane == (int)(__ffs(mB) - 1))
            atomicAdd(&hist_s[base + binB], (int)__popc(mB));
    }

    __syncthreads();
    int* dst = g_part + ((size_t)tile * BB + b) * QB;
    for (int i = t; i < QB; i += NTHREADS) dst[i] = hist_s[i];
}

// ---------------------------------------------------------------------------
// Reduce: out[b] = b1 + sum_i log(sum_tiles hist + 1e-5) * W1[i]
// ---------------------------------------------------------------------------
__global__ void reduce_kernel(const float* __restrict__ W1,
                              const float* __restrict__ b1,
                              float* __restrict__ out)
{
    const int b = blockIdx.x;
    const int t = threadIdx.x;
    float p = 0.f;
    for (int i = t; i < QB; i += 256) {
        int h = 0;
#pragma unroll
        for (int s = 0; s < NTILE; s++)
            h += g_part[((size_t)s * BB + b) * QB + i];
        p += logf((float)h + 1e-5f) * W1[i];
    }
#pragma unroll
    for (int o = 16; o > 0; o >>= 1) p += __shfl_down_sync(0xffffffffu, p, o);

    __shared__ float red[8];
    if ((t & 31) == 0) red[t >> 5] = p;
    __syncthreads();
    if (t == 0) {
        float s = 0.f;
#pragma unroll
        for (int i = 0; i < 8; i++) s += red[i];
        out[b] = s + b1[0];
    }
}

// ---------------------------------------------------------------------------
extern "C" void kernel_launch(void* const* d_in, const int* in_sizes, int n_in,
                              void* d_out, int out_size)
{
    const float* qemb = (const float*)d_in[0];
    const float* demb = (const float*)d_in[1];
    const float* W1   = (const float*)d_in[2];
    const float* b1   = (const float*)d_in[3];
    const int*   qids = (const int*)d_in[5];
    const int*   dids = (const int*)d_in[6];
    for (int i = 0; i < n_in; i++) {
        switch (in_sizes[i]) {
            case BB * QQ * EE:  qemb = (const float*)d_in[i]; break;
            case BB * DD * EE:  demb = (const float*)d_in[i]; break;
            case QB:            W1   = (const float*)d_in[i]; break;
            case 1:             b1   = (const float*)d_in[i]; break;
            case BB * QQ:       qids = (const int*)d_in[i];   break;
            case BB * DD:       dids = (const int*)d_in[i];   break;
            default: break;     // Wg unused (softmax over batch sums to 1)
        }
    }
    float* out = (float*)d_out;

    // 5 launches per call: ncu -s 5 -c 1 lands on simhist (idx5 = call2 pos0)
    dim3 grid(NTILE, BB);                         // (8, 256)
    simhist_kernel<<<grid, NTHREADS>>>(qemb, demb, qids, dids);
    reduce_kernel<<<BB, 256>>>(W1, b1, out);
    nop_kernel<<<1, 1>>>();
    nop_kernel<<<1, 1>>>();
    nop_kernel<<<1, 1>>>();
}

// round 9
// speedup vs baseline: 1.1609x; 1.1609x over previous
#include <cuda_runtime.h>
#include <cuda_bf16.h>
#include <math.h>

// ---------------------------------------------------------------------------
// DRMM matching score, GB300 (sm_103a) — round 9: HYBRID tensor+fma pipes
//   Warps 0-3: bf16-split HMMA.16816 on d-rows [0,128)   (R7 mainloop, n-tiles=7)
//   Warps 4-7: scalar FFMA on d-rows [128,256)           (R1 mainloop)
//   The two pools run on DIFFERENT issue pipes (tensor vs fma) and overlap.
//   Epilogues: HMMA -> nibble/butterfly (R7); scalar -> match_any (R1).
//   Gating branch dropped: softmax over batch sums to exactly 1.
// ---------------------------------------------------------------------------

#define BB   256
#define QQ   50
#define EE   50
#define DD   2000
#define NB   11
#define QB   (QQ * NB)        // 550
#define MT   256              // d-rows per CTA (128 HMMA + 128 scalar)
#define NTILE 8               // 8*256 = 2048 >= 2000
#define ROWB 336              // bf16 tile row stride (bytes)
#define KSTEPS 10
#define NT7  7                // q n-tiles (56 cols >= 50)
#define QROW 52               // fp32 q row stride (floats)

// smem layout (dynamic)
#define SM_B    0             // 64  * 336 = 21504
#define SM_A    21504         // 128 * 336 = 43008 -> 64512
#define SM_Q    64512         // 50*52*4   = 10400 -> 74912
#define SM_HIST 74912         // 550*4     = 2200  -> 77112
#define SM_QV   77112         // 64                -> 77176
#define SM_DV   77176         // 128               -> 77304
#define SM_TOTAL 77376

__device__ int g_part[NTILE * BB * QB];

typedef unsigned long long u64;

__device__ __forceinline__ unsigned smem_u32(const void* p) {
    unsigned a;
    asm("{ .reg .u64 t; cvta.to.shared.u64 t, %1; cvt.u32.u64 %0, t; }"
        : "=r"(a) : "l"(p));
    return a;
}
__device__ __forceinline__ void split2(float x0, float x1,
                                       unsigned& hi, unsigned& lo) {
    __nv_bfloat16 h0 = __float2bfloat16(x0);
    __nv_bfloat16 h1 = __float2bfloat16(x1);
    float r0 = x0 - __bfloat162float(h0);
    float r1 = x1 - __bfloat162float(h1);
    __nv_bfloat16 l0 = __float2bfloat16(r0);
    __nv_bfloat16 l1 = __float2bfloat16(r1);
    hi = (unsigned)__bfloat16_as_ushort(h0) | ((unsigned)__bfloat16_as_ushort(h1) << 16);
    lo = (unsigned)__bfloat16_as_ushort(l0) | ((unsigned)__bfloat16_as_ushort(l1) << 16);
}
__device__ __forceinline__ void ldsm4(unsigned addr, unsigned& r0, unsigned& r1,
                                      unsigned& r2, unsigned& r3) {
    asm volatile("ldmatrix.sync.aligned.m8n8.x4.shared.b16 {%0,%1,%2,%3}, [%4];"
                 : "=r"(r0), "=r"(r1), "=r"(r2), "=r"(r3) : "r"(addr));
}
__device__ __forceinline__ void mma16816(float* c, const unsigned* a,
                                         unsigned b0, unsigned b1) {
    asm volatile(
        "mma.sync.aligned.m16n8k16.row.col.f32.bf16.bf16.f32 "
        "{%0,%1,%2,%3}, {%4,%5,%6,%7}, {%8,%9}, {%0,%1,%2,%3};"
        : "+f"(c[0]), "+f"(c[1]), "+f"(c[2]), "+f"(c[3])
        : "r"(a[0]), "r"(a[1]), "r"(a[2]), "r"(a[3]), "r"(b0), "r"(b1));
}

// ---------------------------------------------------------------------------
__global__ void __launch_bounds__(256, 2)
simhist_kernel(const float* __restrict__ qemb,
               const float* __restrict__ demb,
               const int*   __restrict__ qids,
               const int*   __restrict__ dids)
{
    extern __shared__ char smem[];
    const unsigned sbase = smem_u32(smem);
    const int b    = blockIdx.y;
    const int tile = blockIdx.x;
    const int d0   = tile * MT;
    const int tid  = threadIdx.x;
    const int lane = tid & 31;
    const int w    = tid >> 5;

    int* hist_s = (int*)(smem + SM_HIST);
    float* qf   = (float*)(smem + SM_Q);
    unsigned char* qv_s = (unsigned char*)(smem + SM_QV);
    unsigned char* dv_s = (unsigned char*)(smem + SM_DV);

    for (int i = tid; i < QB; i += 256) hist_s[i] = 0;

    // ---- q staging ----
    if (tid < 64) {                       // bf16 B rows (warps 0-1)
        unsigned* brow = (unsigned*)(smem + SM_B + tid * ROWB);
        if (tid < QQ) {
            const float2* src = (const float2*)(qemb + ((size_t)b * QQ + tid) * EE);
            float2 v[25];
            float ss = 0.f;
#pragma unroll
            for (int c = 0; c < 25; c++) { v[c] = src[c]; ss += v[c].x * v[c].x + v[c].y * v[c].y; }
            const float r = 1.0f / (sqrtf(ss) + 1e-8f);
            qv_s[tid] = (qids[b * QQ + tid] > 0) ? 1 : 0;
#pragma unroll
            for (int c = 0; c < 25; c++) {
                unsigned hi, lo;
                split2(v[c].x * r, v[c].y * r, hi, lo);
                brow[c]      = hi;
                brow[25 + c] = lo;
                brow[50 + c] = hi;
            }
#pragma unroll
            for (int j = 75; j < 84; j++) brow[j] = 0;
        } else {
            qv_s[tid] = 0;
#pragma unroll
            for (int j = 0; j < 84; j++) brow[j] = 0;
        }
    } else if (tid < 64 + QQ) {           // fp32 q rows (warps 2-3)
        const int r = tid - 64;
        const float2* src = (const float2*)(qemb + ((size_t)b * QQ + r) * EE);
        float2 v[25];
        float ss = 0.f;
#pragma unroll
        for (int c = 0; c < 25; c++) { v[c] = src[c]; ss += v[c].x * v[c].x + v[c].y * v[c].y; }
        const float rq = 1.0f / (sqrtf(ss) + 1e-8f);
        float* dst = &qf[r * QROW];
#pragma unroll
        for (int c = 0; c < 25; c++) {
            dst[2 * c]     = v[c].x * rq;
            dst[2 * c + 1] = v[c].y * rq;
        }
        dst[50] = 0.f; dst[51] = 0.f;
    }

    // ---- d staging + compute, split by warp pool ----
    if (w < 4) {
        // ======== HMMA pool: d-rows d0 + [0,128) ========
        {
            const int gd  = d0 + tid;
            const bool ok = (gd < DD);
            const float2* src = (const float2*)(demb + ((size_t)b * DD + (ok ? gd : 0)) * EE);
            float2 v[25];
            float ss = 0.f;
#pragma unroll
            for (int c = 0; c < 25; c++) {
                float2 x = ok ? src[c] : make_float2(0.f, 0.f);
                v[c] = x;
                ss += x.x * x.x + x.y * x.y;
            }
            const float r = 1.0f / (sqrtf(ss) + 1e-8f);
            dv_s[tid] = (ok && dids[b * DD + (ok ? gd : 0)] > 0) ? 1 : 0;

            unsigned* arow = (unsigned*)(smem + SM_A + tid * ROWB);
#pragma unroll
            for (int c = 0; c < 25; c++) {
                unsigned hi, lo;
                split2(v[c].x * r, v[c].y * r, hi, lo);
                arow[c]      = hi;
                arow[25 + c] = hi;
                arow[50 + c] = lo;
            }
#pragma unroll
            for (int j = 75; j < 84; j++) arow[j] = 0;
        }
        __syncthreads();

        float acc[2][NT7][4];
#pragma unroll
        for (int mt = 0; mt < 2; mt++)
#pragma unroll
            for (int nt = 0; nt < NT7; nt++)
#pragma unroll
                for (int ci = 0; ci < 4; ci++) acc[mt][nt][ci] = 0.f;

        const unsigned aAddr = sbase + SM_A + (unsigned)(w * 32 + (lane & 15)) * ROWB
                             + (unsigned)((lane >> 4) * 16);
        const unsigned bAddr = sbase + SM_B
                             + (unsigned)((lane >> 4) * 8 + (lane & 7)) * ROWB
                             + (unsigned)(((lane >> 3) & 1) * 16);

#pragma unroll
        for (int ks = 0; ks < KSTEPS; ks++) {
            unsigned a[2][4];
            ldsm4(aAddr + ks * 32,             a[0][0], a[0][1], a[0][2], a[0][3]);
            ldsm4(aAddr + 16 * ROWB + ks * 32, a[1][0], a[1][1], a[1][2], a[1][3]);
            unsigned bq[4][4];
#pragma unroll
            for (int p = 0; p < 4; p++)
                ldsm4(bAddr + (unsigned)(p * 16 * ROWB) + ks * 32,
                      bq[p][0], bq[p][1], bq[p][2], bq[p][3]);
#pragma unroll
            for (int mt = 0; mt < 2; mt++) {
#pragma unroll
                for (int p = 0; p < 3; p++) {
                    mma16816(acc[mt][2 * p],     a[mt], bq[p][0], bq[p][1]);
                    mma16816(acc[mt][2 * p + 1], a[mt], bq[p][2], bq[p][3]);
                }
                mma16816(acc[mt][6], a[mt], bq[3][0], bq[3][1]);   // nt=6 only
            }
        }

        // nibble/butterfly epilogue (R7)
        const int r0 = w * 32 + (lane >> 2);
        const unsigned dvq = (unsigned)dv_s[r0]
                           | ((unsigned)dv_s[r0 + 8]  << 1)
                           | ((unsigned)dv_s[r0 + 16] << 2)
                           | ((unsigned)dv_s[r0 + 24] << 3);
        const int copyidx = lane >> 2;
        const int cbase   = (lane & 3) * 2;

#pragma unroll
        for (int nt = 0; nt < NT7; nt++) {
#pragma unroll
            for (int half = 0; half < 2; half++) {
                const int q = nt * 8 + cbase + half;
                u64 h = 0ull;
                {
                    float s0 = acc[0][nt][half];
                    float s1 = acc[0][nt][half + 2];
                    float s2 = acc[1][nt][half];
                    float s3 = acc[1][nt][half + 2];
                    int b0 = min(max((int)fmaf(s0, 5.0f, 5.000005f), 0), NB - 1);
                    int b1 = min(max((int)fmaf(s1, 5.0f, 5.000005f), 0), NB - 1);
                    int b2 = min(max((int)fmaf(s2, 5.0f, 5.000005f), 0), NB - 1);
                    int b3 = min(max((int)fmaf(s3, 5.0f, 5.000005f), 0), NB - 1);
                    h += (u64)(dvq & 1u)        << (b0 * 4);
                    h += (u64)((dvq >> 1) & 1u) << (b1 * 4);
                    h += (u64)((dvq >> 2) & 1u) << (b2 * 4);
                    h += (u64)((dvq >> 3) & 1u) << (b3 * 4);
                }
                u64 he = h & 0x0F0F0F0F0F0F0F0Full;
                u64 ho = (h >> 4) & 0x0F0F0F0F0F0F0F0Full;
#pragma unroll
                for (int o = 4; o < 32; o <<= 1) {
                    he += __shfl_xor_sync(0xffffffffu, he, o);
                    ho += __shfl_xor_sync(0xffffffffu, ho, o);
                }
                if (((nt * 2 + half) & 7) == copyidx && q < QQ && qv_s[q]) {
#pragma unroll
                    for (int bin = 0; bin < NB; bin++) {
                        u64 src = (bin & 1) ? ho : he;
                        int cnt = (int)((src >> ((bin >> 1) * 8)) & 0xFFull);
                        if (cnt) atomicAdd(&hist_s[q * NB + bin], cnt);
                    }
                }
            }
        }
    } else {
        // ======== scalar pool: d-rows d0 + 128 + [0,128) ========
        const int gd  = d0 + tid;           // tid in [128,256) -> d0+128..d0+255
        const bool ok = (gd < DD);
        float a[52];
        {
            const float2* src = (const float2*)(demb + ((size_t)b * DD + (ok ? gd : 0)) * EE);
            float ss = 0.f;
#pragma unroll
            for (int c = 0; c < 25; c++) {
                float2 x = ok ? src[c] : make_float2(0.f, 0.f);
                a[2 * c] = x.x; a[2 * c + 1] = x.y;
                ss += x.x * x.x + x.y * x.y;
            }
            a[50] = a[51] = 0.f;
            const float r = 1.0f / (sqrtf(ss) + 1e-8f);
#pragma unroll
            for (int e = 0; e < 50; e++) a[e] *= r;
        }
        const bool add = ok && (dids[b * DD + (ok ? gd : 0)] > 0);
        const unsigned vb = __ballot_sync(0xffffffffu, add);
        __syncthreads();

        for (int q = 0; q < QQ; q++) {
            if (!qv_s[q]) continue;
            const float4* wv4 = (const float4*)&qf[q * QROW];
            float s0 = 0.f, s1 = 0.f, s2 = 0.f, s3 = 0.f;
#pragma unroll
            for (int c = 0; c < 13; c++) {
                float4 wv = wv4[c];
                s0 = fmaf(a[4 * c],     wv.x, s0);
                s1 = fmaf(a[4 * c + 1], wv.y, s1);
                s2 = fmaf(a[4 * c + 2], wv.z, s2);
                s3 = fmaf(a[4 * c + 3], wv.w, s3);
            }
            float sim = (s0 + s1) + (s2 + s3);
            int bin = (int)fmaf(sim, 5.0f, 5.000005f);
            bin = min(max(bin, 0), NB - 1);
            unsigned m = __match_any_sync(0xffffffffu, bin) & vb;
            if (add && lane == (int)(__ffs(m) - 1))
                atomicAdd(&hist_s[q * NB + bin], (int)__popc(m));
        }
    }

    __syncthreads();
    int* dst = g_part + ((size_t)tile * BB + b) * QB;
    for (int i = tid; i < QB; i += 256) dst[i] = hist_s[i];
}

// ---------------------------------------------------------------------------
__global__ void reduce_kernel(const float* __restrict__ W1,
                              const float* __restrict__ b1,
                              float* __restrict__ out)
{
    const int b = blockIdx.x;
    const int t = threadIdx.x;
    float p = 0.f;
    for (int i = t; i < QB; i += 256) {
        int h = 0;
#pragma unroll
        for (int s = 0; s < NTILE; s++)
            h += g_part[((size_t)s * BB + b) * QB + i];
        p += logf((float)h + 1e-5f) * W1[i];
    }
#pragma unroll
    for (int o = 16; o > 0; o >>= 1) p += __shfl_down_sync(0xffffffffu, p, o);

    __shared__ float red[8];
    if ((t & 31) == 0) red[t >> 5] = p;
    __syncthreads();
    if (t == 0) {
        float s = 0.f;
#pragma unroll
        for (int i = 0; i < 8; i++) s += red[i];
        out[b] = s + b1[0];
    }
}

// ---------------------------------------------------------------------------
extern "C" void kernel_launch(void* const* d_in, const int* in_sizes, int n_in,
                              void* d_out, int out_size)
{
    const float* qemb = (const float*)d_in[0];
    const float* demb = (const float*)d_in[1];
    const float* W1   = (const float*)d_in[2];
    const float* b1   = (const float*)d_in[3];
    const int*   qids = (const int*)d_in[5];
    const int*   dids = (const int*)d_in[6];
    for (int i = 0; i < n_in; i++) {
        switch (in_sizes[i]) {
            case BB * QQ * EE:  qemb = (const float*)d_in[i]; break;
            case BB * DD * EE:  demb = (const float*)d_in[i]; break;
            case QB:            W1   = (const float*)d_in[i]; break;
            case 1:             b1   = (const float*)d_in[i]; break;
            case BB * QQ:       qids = (const int*)d_in[i];   break;
            case BB * DD:       dids = (const int*)d_in[i];   break;
            default: break;     // Wg unused (softmax over batch sums to 1)
        }
    }
    float* out = (float*)d_out;

    static int smem_set = 0;
    if (!smem_set) {
        cudaFuncSetAttribute(simhist_kernel,
                             cudaFuncAttributeMaxDynamicSharedMemorySize, SM_TOTAL);
        smem_set = 1;
    }

    dim3 grid(NTILE, BB);                         // (8, 256)
    simhist_kernel<<<grid, 256, SM_TOTAL>>>(qemb, demb, qids, dids);
    reduce_kernel<<<BB, 256>>>(W1, b1, out);
}

// round 10
// speedup vs baseline: 1.1655x; 1.0039x over previous
#include <cuda_runtime.h>
#include <cuda_bf16.h>
#include <math.h>

// ---------------------------------------------------------------------------
// DRMM matching score, GB300 (sm_103a) — round 10: R7 HMMA, N-tiles trimmed 8->7
//   R7 is HMMA-throughput-bound (T_CTA ~= 280 HMMA/SMSP x rt~32) -> removing
//   the unused q-columns 56..63 cuts 12.5% of all HMMA directly.
//   Batch-split launches so ncu (-s 5 -c 1) captures the MAIN kernel (idx5=simB).
//   Gating branch dropped: softmax over batch sums to exactly 1.
// ---------------------------------------------------------------------------

#define BB   256
#define QQ   50
#define EE   50
#define DD   2000
#define NB   11
#define QB   (QQ * NB)        // 550
#define MT   128
#define NTILE 16
#define ROWB 336              // smem row stride bytes (168 bf16)
#define KSTEPS 10             // K=160 / 16
#define NT7  7                // q n-tiles (56 >= 50)

#define SM_B    0             // 64 * 336  = 21504 (rows 56-63 allocated, unused)
#define SM_A    21504         // 128 * 336 = 43008 -> 64512
#define SM_HIST 64512         // 550 * 4            -> 66712
#define SM_QV   66712         // 64 bytes           -> 66776
#define SM_DV   66776         // 128 bytes          -> 66904
#define SM_TOTAL 66944

__device__ int g_part[NTILE * BB * QB];

typedef unsigned long long u64;

__global__ void nop_kernel() {}

__device__ __forceinline__ unsigned smem_u32(const void* p) {
    unsigned a;
    asm("{ .reg .u64 t; cvta.to.shared.u64 t, %1; cvt.u32.u64 %0, t; }"
        : "=r"(a) : "l"(p));
    return a;
}
__device__ __forceinline__ void split2(float x0, float x1,
                                       unsigned& hi, unsigned& lo) {
    __nv_bfloat16 h0 = __float2bfloat16(x0);
    __nv_bfloat16 h1 = __float2bfloat16(x1);
    float r0 = x0 - __bfloat162float(h0);
    float r1 = x1 - __bfloat162float(h1);
    __nv_bfloat16 l0 = __float2bfloat16(r0);
    __nv_bfloat16 l1 = __float2bfloat16(r1);
    hi = (unsigned)__bfloat16_as_ushort(h0) | ((unsigned)__bfloat16_as_ushort(h1) << 16);
    lo = (unsigned)__bfloat16_as_ushort(l0) | ((unsigned)__bfloat16_as_ushort(l1) << 16);
}
__device__ __forceinline__ void ldsm4(unsigned addr, unsigned& r0, unsigned& r1,
                                      unsigned& r2, unsigned& r3) {
    asm volatile("ldmatrix.sync.aligned.m8n8.x4.shared.b16 {%0,%1,%2,%3}, [%4];"
                 : "=r"(r0), "=r"(r1), "=r"(r2), "=r"(r3) : "r"(addr));
}
__device__ __forceinline__ void ldsm2(unsigned addr, unsigned& r0, unsigned& r1) {
    asm volatile("ldmatrix.sync.aligned.m8n8.x2.shared.b16 {%0,%1}, [%2];"
                 : "=r"(r0), "=r"(r1) : "r"(addr));
}
__device__ __forceinline__ void mma16816(float* c, const unsigned* a,
                                         unsigned b0, unsigned b1) {
    asm volatile(
        "mma.sync.aligned.m16n8k16.row.col.f32.bf16.bf16.f32 "
        "{%0,%1,%2,%3}, {%4,%5,%6,%7}, {%8,%9}, {%0,%1,%2,%3};"
        : "+f"(c[0]), "+f"(c[1]), "+f"(c[2]), "+f"(c[3])
        : "r"(a[0]), "r"(a[1]), "r"(a[2]), "r"(a[3]), "r"(b0), "r"(b1));
}

// ---------------------------------------------------------------------------
__global__ void __launch_bounds__(128, 3)
simhist_kernel(const float* __restrict__ qemb,
               const float* __restrict__ demb,
               const int*   __restrict__ qids,
               const int*   __restrict__ dids,
               int b0)
{
    extern __shared__ char smem[];
    const unsigned sbase = smem_u32(smem);
    const int b    = b0 + blockIdx.y;
    const int tile = blockIdx.x;
    const int tid  = threadIdx.x;
    const int lane = tid & 31;
    const int w    = tid >> 5;

    int* hist_s = (int*)(smem + SM_HIST);
    unsigned char* qv_s = (unsigned char*)(smem + SM_QV);
    unsigned char* dv_s = (unsigned char*)(smem + SM_DV);

    for (int i = tid; i < QB; i += 128) hist_s[i] = 0;

    // ---- build B tile (q side): rows 0..55 (rows 56-63 never used) ----
    if (tid < 56) {
        unsigned* brow = (unsigned*)(smem + SM_B + tid * ROWB);
        if (tid < QQ) {
            const float2* src = (const float2*)(qemb + ((size_t)b * QQ + tid) * EE);
            float2 v[25];
            float ss = 0.f;
#pragma unroll
            for (int c = 0; c < 25; c++) { v[c] = src[c]; ss += v[c].x * v[c].x + v[c].y * v[c].y; }
            const float r = 1.0f / (sqrtf(ss) + 1e-8f);
            qv_s[tid] = (qids[b * QQ + tid] > 0) ? 1 : 0;
#pragma unroll
            for (int c = 0; c < 25; c++) {
                unsigned hi, lo;
                split2(v[c].x * r, v[c].y * r, hi, lo);
                brow[c]      = hi;
                brow[25 + c] = lo;
                brow[50 + c] = hi;
            }
#pragma unroll
            for (int j = 75; j < 84; j++) brow[j] = 0;
        } else {
            qv_s[tid] = 0;
#pragma unroll
            for (int j = 0; j < 84; j++) brow[j] = 0;
        }
    }

    // ---- build A tile (d side): each thread one row ----
    {
        const int gd  = tile * MT + tid;
        const bool ok = (gd < DD);
        const float2* src = (const float2*)(demb + ((size_t)b * DD + (ok ? gd : 0)) * EE);
        float2 v[25];
        float ss = 0.f;
#pragma unroll
        for (int c = 0; c < 25; c++) {
            float2 x = ok ? src[c] : make_float2(0.f, 0.f);
            v[c] = x;
            ss += x.x * x.x + x.y * x.y;
        }
        const float r = 1.0f / (sqrtf(ss) + 1e-8f);
        dv_s[tid] = (ok && dids[b * DD + (ok ? gd : 0)] > 0) ? 1 : 0;

        unsigned* arow = (unsigned*)(smem + SM_A + tid * ROWB);
#pragma unroll
        for (int c = 0; c < 25; c++) {
            unsigned hi, lo;
            split2(v[c].x * r, v[c].y * r, hi, lo);
            arow[c]      = hi;
            arow[25 + c] = hi;
            arow[50 + c] = lo;
        }
#pragma unroll
        for (int j = 75; j < 84; j++) arow[j] = 0;
    }
    __syncthreads();

    // ---- HMMA mainloop (nt = 7: q-cols 0..55 only) ----
    float acc[2][NT7][4];
#pragma unroll
    for (int mt = 0; mt < 2; mt++)
#pragma unroll
        for (int nt = 0; nt < NT7; nt++)
#pragma unroll
            for (int ci = 0; ci < 4; ci++) acc[mt][nt][ci] = 0.f;

    const unsigned aAddr = sbase + SM_A + (unsigned)(w * 32 + (lane & 15)) * ROWB
                         + (unsigned)((lane >> 4) * 16);
    const unsigned bAddr = sbase + SM_B
                         + (unsigned)((lane >> 4) * 8 + (lane & 7)) * ROWB
                         + (unsigned)(((lane >> 3) & 1) * 16);
    const unsigned bAddr2 = sbase + SM_B
                          + (unsigned)(48 + (lane & 7)) * ROWB
                          + (unsigned)(((lane >> 3) & 1) * 16);   // rows 48-55 (x2)

#pragma unroll
    for (int ks = 0; ks < KSTEPS; ks++) {
        unsigned a[2][4];
        ldsm4(aAddr + ks * 32,             a[0][0], a[0][1], a[0][2], a[0][3]);
        ldsm4(aAddr + 16 * ROWB + ks * 32, a[1][0], a[1][1], a[1][2], a[1][3]);
        unsigned bq[3][4];
#pragma unroll
        for (int p = 0; p < 3; p++)
            ldsm4(bAddr + (unsigned)(p * 16 * ROWB) + ks * 32,
                  bq[p][0], bq[p][1], bq[p][2], bq[p][3]);
        unsigned b6lo, b6hi;
        ldsm2(bAddr2 + ks * 32, b6lo, b6hi);     // nt=6 pair (rows 48-55)
#pragma unroll
        for (int mt = 0; mt < 2; mt++) {
#pragma unroll
            for (int p = 0; p < 3; p++) {
                mma16816(acc[mt][2 * p],     a[mt], bq[p][0], bq[p][1]);
                mma16816(acc[mt][2 * p + 1], a[mt], bq[p][2], bq[p][3]);
            }
            mma16816(acc[mt][6], a[mt], b6lo, b6hi);
        }
    }

    // ---- epilogue: nibble hist + butterfly (R7-proven) ----
    const int r0 = w * 32 + (lane >> 2);
    const unsigned dvq = (unsigned)dv_s[r0]
                       | ((unsigned)dv_s[r0 + 8]  << 1)
                       | ((unsigned)dv_s[r0 + 16] << 2)
                       | ((unsigned)dv_s[r0 + 24] << 3);
    const int copyidx = lane >> 2;
    const int cbase   = (lane & 3) * 2;

#pragma unroll
    for (int nt = 0; nt < NT7; nt++) {
#pragma unroll
        for (int half = 0; half < 2; half++) {
            const int q = nt * 8 + cbase + half;
            u64 h = 0ull;
            {
                float s0 = acc[0][nt][half];
                float s1 = acc[0][nt][half + 2];
                float s2 = acc[1][nt][half];
                float s3 = acc[1][nt][half + 2];
                int c0 = min(max((int)fmaf(s0, 5.0f, 5.000005f), 0), NB - 1);
                int c1 = min(max((int)fmaf(s1, 5.0f, 5.000005f), 0), NB - 1);
                int c2 = min(max((int)fmaf(s2, 5.0f, 5.000005f), 0), NB - 1);
                int c3 = min(max((int)fmaf(s3, 5.0f, 5.000005f), 0), NB - 1);
                h += (u64)(dvq & 1u)        << (c0 * 4);
                h += (u64)((dvq >> 1) & 1u) << (c1 * 4);
                h += (u64)((dvq >> 2) & 1u) << (c2 * 4);
                h += (u64)((dvq >> 3) & 1u) << (c3 * 4);
            }
            u64 he = h & 0x0F0F0F0F0F0F0F0Full;
            u64 ho = (h >> 4) & 0x0F0F0F0F0F0F0F0Full;
#pragma unroll
            for (int o = 4; o < 32; o <<= 1) {
                he += __shfl_xor_sync(0xffffffffu, he, o);
                ho += __shfl_xor_sync(0xffffffffu, ho, o);
            }
            if (((nt * 2 + half) & 7) == copyidx && q < QQ && qv_s[q]) {
#pragma unroll
                for (int bin = 0; bin < NB; bin++) {
                    u64 src = (bin & 1) ? ho : he;
                    int cnt = (int)((src >> ((bin >> 1) * 8)) & 0xFFull);
                    if (cnt) atomicAdd(&hist_s[q * NB + bin], cnt);
                }
            }
        }
    }

    __syncthreads();
    int* dst = g_part + ((size_t)tile * BB + b) * QB;
    for (int i = tid; i < QB; i += 128) dst[i] = hist_s[i];
}

// ---------------------------------------------------------------------------
__global__ void reduce_kernel(const float* __restrict__ W1,
                              const float* __restrict__ b1,
                              float* __restrict__ out)
{
    const int b = blockIdx.x;
    const int t = threadIdx.x;
    float p = 0.f;
    for (int i = t; i < QB; i += 256) {
        int h = 0;
#pragma unroll
        for (int s = 0; s < NTILE; s++)
            h += g_part[((size_t)s * BB + b) * QB + i];
        p += logf((float)h + 1e-5f) * W1[i];
    }
#pragma unroll
    for (int o = 16; o > 0; o >>= 1) p += __shfl_down_sync(0xffffffffu, p, o);

    __shared__ float red[8];
    if ((t & 31) == 0) red[t >> 5] = p;
    __syncthreads();
    if (t == 0) {
        float s = 0.f;
#pragma unroll
        for (int i = 0; i < 8; i++) s += red[i];
        out[b] = s + b1[0];
    }
}

// ---------------------------------------------------------------------------
extern "C" void kernel_launch(void* const* d_in, const int* in_sizes, int n_in,
                              void* d_out, int out_size)
{
    const float* qemb = (const float*)d_in[0];
    const float* demb = (const float*)d_in[1];
    const float* W1   = (const float*)d_in[2];
    const float* b1   = (const float*)d_in[3];
    const int*   qids = (const int*)d_in[5];
    const int*   dids = (const int*)d_in[6];
    for (int i = 0; i < n_in; i++) {
        switch (in_sizes[i]) {
            case BB * QQ * EE:  qemb = (const float*)d_in[i]; break;
            case BB * DD * EE:  demb = (const float*)d_in[i]; break;
            case QB:            W1   = (const float*)d_in[i]; break;
            case 1:             b1   = (const float*)d_in[i]; break;
            case BB * QQ:       qids = (const int*)d_in[i];   break;
            case BB * DD:       dids = (const int*)d_in[i];   break;
            default: break;     // Wg unused (softmax over batch sums to 1)
        }
    }
    float* out = (float*)d_out;

    static int smem_set = 0;
    if (!smem_set) {
        cudaFuncSetAttribute(simhist_kernel,
                             cudaFuncAttributeMaxDynamicSharedMemorySize, SM_TOTAL);
        smem_set = 1;
    }

    // 4 launches/call: [simA, simB, reduce, nop] -> ncu -s 5 lands on simB (main)
    dim3 grid(NTILE, BB / 2);                     // (16, 128) each
    simhist_kernel<<<grid, 128, SM_TOTAL>>>(qemb, demb, qids, dids, 0);
    simhist_kernel<<<grid, 128, SM_TOTAL>>>(qemb, demb, qids, dids, BB / 2);
    reduce_kernel<<<BB, 256>>>(W1, b1, out);
    nop_kernel<<<1, 1>>>();
}

// round 11
// speedup vs baseline: 1.2568x; 1.0783x over previous
#include <cuda_runtime.h>
#include <cuda_bf16.h>
#include <math.h>

// ---------------------------------------------------------------------------
// DRMM matching score, GB300 (sm_103a) — round 11:
//   = round 7 (129.5us best) + N-tile trim 8->7 (q-cols 56..63 never computed),
//   single launch (round 10 proved the split launch costs ~20us in tails).
//   HMMA-throughput-bound -> 12.5% fewer HMMA converts directly to time.
//   Gating branch dropped: softmax over batch sums to exactly 1.
// ---------------------------------------------------------------------------

#define BB   256
#define QQ   50
#define EE   50
#define DD   2000
#define NB   11
#define QB   (QQ * NB)        // 550
#define MT   128
#define NTILE 16
#define ROWB 336              // smem row stride bytes (168 bf16) — conflict-free
#define KSTEPS 10             // K=160 / 16
#define NT7  7                // q n-tiles (56 >= 50)

#define SM_B    0             // 64 * 336  = 21504
#define SM_A    21504         // 128 * 336 = 43008 -> 64512
#define SM_HIST 64512         // 550 * 4            -> 66712
#define SM_QV   66712         // 64 bytes           -> 66776
#define SM_DV   66776         // 128 bytes          -> 66904
#define SM_TOTAL 66944

__device__ int g_part[NTILE * BB * QB];

typedef unsigned long long u64;

__device__ __forceinline__ unsigned smem_u32(const void* p) {
    unsigned a;
    asm("{ .reg .u64 t; cvta.to.shared.u64 t, %1; cvt.u32.u64 %0, t; }"
        : "=r"(a) : "l"(p));
    return a;
}
__device__ __forceinline__ void split2(float x0, float x1,
                                       unsigned& hi, unsigned& lo) {
    __nv_bfloat16 h0 = __float2bfloat16(x0);
    __nv_bfloat16 h1 = __float2bfloat16(x1);
    float r0 = x0 - __bfloat162float(h0);
    float r1 = x1 - __bfloat162float(h1);
    __nv_bfloat16 l0 = __float2bfloat16(r0);
    __nv_bfloat16 l1 = __float2bfloat16(r1);
    hi = (unsigned)__bfloat16_as_ushort(h0) | ((unsigned)__bfloat16_as_ushort(h1) << 16);
    lo = (unsigned)__bfloat16_as_ushort(l0) | ((unsigned)__bfloat16_as_ushort(l1) << 16);
}
__device__ __forceinline__ void ldsm4(unsigned addr, unsigned& r0, unsigned& r1,
                                      unsigned& r2, unsigned& r3) {
    asm volatile("ldmatrix.sync.aligned.m8n8.x4.shared.b16 {%0,%1,%2,%3}, [%4];"
                 : "=r"(r0), "=r"(r1), "=r"(r2), "=r"(r3) : "r"(addr));
}
__device__ __forceinline__ void ldsm2(unsigned addr, unsigned& r0, unsigned& r1) {
    asm volatile("ldmatrix.sync.aligned.m8n8.x2.shared.b16 {%0,%1}, [%2];"
                 : "=r"(r0), "=r"(r1) : "r"(addr));
}
__device__ __forceinline__ void mma16816(float* c, const unsigned* a,
                                         unsigned b0, unsigned b1) {
    asm volatile(
        "mma.sync.aligned.m16n8k16.row.col.f32.bf16.bf16.f32 "
        "{%0,%1,%2,%3}, {%4,%5,%6,%7}, {%8,%9}, {%0,%1,%2,%3};"
        : "+f"(c[0]), "+f"(c[1]), "+f"(c[2]), "+f"(c[3])
        : "r"(a[0]), "r"(a[1]), "r"(a[2]), "r"(a[3]), "r"(b0), "r"(b1));
}

// ---------------------------------------------------------------------------
__global__ void __launch_bounds__(128, 3)
simhist_kernel(const float* __restrict__ qemb,
               const float* __restrict__ demb,
               const int*   __restrict__ qids,
               const int*   __restrict__ dids)
{
    extern __shared__ char smem[];
    const unsigned sbase = smem_u32(smem);
    const int b    = blockIdx.y;
    const int tile = blockIdx.x;
    const int tid  = threadIdx.x;
    const int lane = tid & 31;
    const int w    = tid >> 5;

    int* hist_s = (int*)(smem + SM_HIST);
    unsigned char* qv_s = (unsigned char*)(smem + SM_QV);
    unsigned char* dv_s = (unsigned char*)(smem + SM_DV);

    for (int i = tid; i < QB; i += 128) hist_s[i] = 0;

    // ---- build B tile (q side): rows 0..55 used ----
    if (tid < 56) {
        unsigned* brow = (unsigned*)(smem + SM_B + tid * ROWB);
        if (tid < QQ) {
            const float2* src = (const float2*)(qemb + ((size_t)b * QQ + tid) * EE);
            float2 v[25];
            float ss = 0.f;
#pragma unroll
            for (int c = 0; c < 25; c++) { v[c] = src[c]; ss += v[c].x * v[c].x + v[c].y * v[c].y; }
            const float r = 1.0f / (sqrtf(ss) + 1e-8f);
            qv_s[tid] = (qids[b * QQ + tid] > 0) ? 1 : 0;
#pragma unroll
            for (int c = 0; c < 25; c++) {
                unsigned hi, lo;
                split2(v[c].x * r, v[c].y * r, hi, lo);
                brow[c]      = hi;
                brow[25 + c] = lo;
                brow[50 + c] = hi;
            }
#pragma unroll
            for (int j = 75; j < 84; j++) brow[j] = 0;
        } else {
            qv_s[tid] = 0;
#pragma unroll
            for (int j = 0; j < 84; j++) brow[j] = 0;
        }
    }

    // ---- build A tile (d side): each thread one row ----
    {
        const int gd  = tile * MT + tid;
        const bool ok = (gd < DD);
        const float2* src = (const float2*)(demb + ((size_t)b * DD + (ok ? gd : 0)) * EE);
        float2 v[25];
        float ss = 0.f;
#pragma unroll
        for (int c = 0; c < 25; c++) {
            float2 x = ok ? src[c] : make_float2(0.f, 0.f);
            v[c] = x;
            ss += x.x * x.x + x.y * x.y;
        }
        const float r = 1.0f / (sqrtf(ss) + 1e-8f);
        dv_s[tid] = (ok && dids[b * DD + (ok ? gd : 0)] > 0) ? 1 : 0;

        unsigned* arow = (unsigned*)(smem + SM_A + tid * ROWB);
#pragma unroll
        for (int c = 0; c < 25; c++) {
            unsigned hi, lo;
            split2(v[c].x * r, v[c].y * r, hi, lo);
            arow[c]      = hi;
            arow[25 + c] = hi;
            arow[50 + c] = lo;
        }
#pragma unroll
        for (int j = 75; j < 84; j++) arow[j] = 0;
    }
    __syncthreads();

    // ---- HMMA mainloop (nt = 7: q-cols 0..55 only) ----
    float acc[2][NT7][4];
#pragma unroll
    for (int mt = 0; mt < 2; mt++)
#pragma unroll
        for (int nt = 0; nt < NT7; nt++)
#pragma unroll
            for (int ci = 0; ci < 4; ci++) acc[mt][nt][ci] = 0.f;

    const unsigned aAddr = sbase + SM_A + (unsigned)(w * 32 + (lane & 15)) * ROWB
                         + (unsigned)((lane >> 4) * 16);
    const unsigned bAddr = sbase + SM_B
                         + (unsigned)((lane >> 4) * 8 + (lane & 7)) * ROWB
                         + (unsigned)(((lane >> 3) & 1) * 16);
    const unsigned bAddr2 = sbase + SM_B
                          + (unsigned)(48 + (lane & 7)) * ROWB
                          + (unsigned)(((lane >> 3) & 1) * 16);   // rows 48-55 (x2)

#pragma unroll
    for (int ks = 0; ks < KSTEPS; ks++) {
        unsigned a[2][4];
        ldsm4(aAddr + ks * 32,             a[0][0], a[0][1], a[0][2], a[0][3]);
        ldsm4(aAddr + 16 * ROWB + ks * 32, a[1][0], a[1][1], a[1][2], a[1][3]);
        unsigned bq[3][4];
#pragma unroll
        for (int p = 0; p < 3; p++)
            ldsm4(bAddr + (unsigned)(p * 16 * ROWB) + ks * 32,
                  bq[p][0], bq[p][1], bq[p][2], bq[p][3]);
        unsigned b6lo, b6hi;
        ldsm2(bAddr2 + ks * 32, b6lo, b6hi);     // nt=6 pair (rows 48-55)
#pragma unroll
        for (int mt = 0; mt < 2; mt++) {
#pragma unroll
            for (int p = 0; p < 3; p++) {
                mma16816(acc[mt][2 * p],     a[mt], bq[p][0], bq[p][1]);
                mma16816(acc[mt][2 * p + 1], a[mt], bq[p][2], bq[p][3]);
            }
            mma16816(acc[mt][6], a[mt], b6lo, b6hi);
        }
    }

    // ---- epilogue: nibble hist + butterfly (R7-proven) ----
    const int r0 = w * 32 + (lane >> 2);
    const unsigned dvq = (unsigned)dv_s[r0]
                       | ((unsigned)dv_s[r0 + 8]  << 1)
                       | ((unsigned)dv_s[r0 + 16] << 2)
                       | ((unsigned)dv_s[r0 + 24] << 3);
    const int copyidx = lane >> 2;
    const int cbase   = (lane & 3) * 2;

#pragma unroll
    for (int nt = 0; nt < NT7; nt++) {
#pragma unroll
        for (int half = 0; half < 2; half++) {
            const int q = nt * 8 + cbase + half;
            u64 h = 0ull;
            {
                float s0 = acc[0][nt][half];
                float s1 = acc[0][nt][half + 2];
                float s2 = acc[1][nt][half];
                float s3 = acc[1][nt][half + 2];
                int c0 = min(max((int)fmaf(s0, 5.0f, 5.000005f), 0), NB - 1);
                int c1 = min(max((int)fmaf(s1, 5.0f, 5.000005f), 0), NB - 1);
                int c2 = min(max((int)fmaf(s2, 5.0f, 5.000005f), 0), NB - 1);
                int c3 = min(max((int)fmaf(s3, 5.0f, 5.000005f), 0), NB - 1);
                h += (u64)(dvq & 1u)        << (c0 * 4);
                h += (u64)((dvq >> 1) & 1u) << (c1 * 4);
                h += (u64)((dvq >> 2) & 1u) << (c2 * 4);
                h += (u64)((dvq >> 3) & 1u) << (c3 * 4);
            }
            u64 he = h & 0x0F0F0F0F0F0F0F0Full;
            u64 ho = (h >> 4) & 0x0F0F0F0F0F0F0F0Full;
#pragma unroll
            for (int o = 4; o < 32; o <<= 1) {
                he += __shfl_xor_sync(0xffffffffu, he, o);
                ho += __shfl_xor_sync(0xffffffffu, ho, o);
            }
            if (((nt * 2 + half) & 7) == copyidx && q < QQ && qv_s[q]) {
#pragma unroll
                for (int bin = 0; bin < NB; bin++) {
                    u64 src = (bin & 1) ? ho : he;
                    int cnt = (int)((src >> ((bin >> 1) * 8)) & 0xFFull);
                    if (cnt) atomicAdd(&hist_s[q * NB + bin], cnt);
                }
            }
        }
    }

    __syncthreads();
    int* dst = g_part + ((size_t)tile * BB + b) * QB;
    for (int i = tid; i < QB; i += 128) dst[i] = hist_s[i];
}

// ---------------------------------------------------------------------------
__global__ void reduce_kernel(const float* __restrict__ W1,
                              const float* __restrict__ b1,
                              float* __restrict__ out)
{
    const int b = blockIdx.x;
    const int t = threadIdx.x;
    float p = 0.f;
    for (int i = t; i < QB; i += 256) {
        int h = 0;
#pragma unroll
        for (int s = 0; s < NTILE; s++)
            h += g_part[((size_t)s * BB + b) * QB + i];
        p += logf((float)h + 1e-5f) * W1[i];
    }
#pragma unroll
    for (int o = 16; o > 0; o >>= 1) p += __shfl_down_sync(0xffffffffu, p, o);

    __shared__ float red[8];
    if ((t & 31) == 0) red[t >> 5] = p;
    __syncthreads();
    if (t == 0) {
        float s = 0.f;
#pragma unroll
        for (int i = 0; i < 8; i++) s += red[i];
        out[b] = s + b1[0];
    }
}

// ---------------------------------------------------------------------------
extern "C" void kernel_launch(void* const* d_in, const int* in_sizes, int n_in,
                              void* d_out, int out_size)
{
    const float* qemb = (const float*)d_in[0];
    const float* demb = (const float*)d_in[1];
    const float* W1   = (const float*)d_in[2];
    const float* b1   = (const float*)d_in[3];
    const int*   qids = (const int*)d_in[5];
    const int*   dids = (const int*)d_in[6];
    for (int i = 0; i < n_in; i++) {
        switch (in_sizes[i]) {
            case BB * QQ * EE:  qemb = (const float*)d_in[i]; break;
            case BB * DD * EE:  demb = (const float*)d_in[i]; break;
            case QB:            W1   = (const float*)d_in[i]; break;
            case 1:             b1   = (const float*)d_in[i]; break;
            case BB * QQ:       qids = (const int*)d_in[i];   break;
            case BB * DD:       dids = (const int*)d_in[i];   break;
            default: break;     // Wg unused (softmax over batch sums to 1)
        }
    }
    float* out = (float*)d_out;

    static int smem_set = 0;
    if (!smem_set) {
        cudaFuncSetAttribute(simhist_kernel,
                             cudaFuncAttributeMaxDynamicSharedMemorySize, SM_TOTAL);
        smem_set = 1;
    }

    dim3 grid(NTILE, BB);                         // (16, 256) — single launch
    simhist_kernel<<<grid, 128, SM_TOTAL>>>(qemb, demb, qids, dids);
    reduce_kernel<<<BB, 256>>>(W1, b1, out);
}